// round 4
// baseline (speedup 1.0000x reference)
#include <cuda_runtime.h>
#include <math.h>

#define BB   2
#define SSQ  4096
#define DDIM 768
#define HHD  12
#define DKK  64
#define FFD  3072
#define MTOT (BB*SSQ)        // 8192 rows
#define EPSV 1e-5f

// ---------------- scratch (device globals; no allocations allowed) ----------
__device__ float g_q  [MTOT*DDIM];
__device__ float g_k  [MTOT*DDIM];
__device__ float g_v  [MTOT*DDIM];
__device__ float g_ctx[MTOT*DDIM];
__device__ float g_att[MTOT*DDIM];
__device__ float g_x1 [MTOT*DDIM];
__device__ float g_ffh[MTOT*FFD];
__device__ float g_ff2[MTOT*DDIM];

// ---------------- tiled SGEMM: C[M,N] = A[M,K] @ W[K,N] + bias (opt ReLU) ---
// 128x128 block tile, BK=8, 256 threads, 8x8 per thread.
// M % 128 == 0, N % 128 == 0, K % 8 == 0 (all true here).
template<bool RELU>
__global__ __launch_bounds__(256) void sgemm_bias(
    const float* __restrict__ A, const float* __restrict__ W,
    const float* __restrict__ bias, float* __restrict__ C,
    int M, int N, int K)
{
    __shared__ float As[8*128];   // transposed: As[k][m]
    __shared__ float Bs[8*128];   // Bs[k][n]

    const int tid  = threadIdx.x;
    const int row0 = blockIdx.y * 128;
    const int col0 = blockIdx.x * 128;

    const int irA = tid >> 1,  icA = (tid & 1) << 2;    // A: 128 rows x 8 cols
    const int irB = tid >> 5,  icB = (tid & 31) << 2;   // W: 8 rows x 128 cols
    const int tr  = tid >> 4,  tc  = tid & 15;          // 16x16 thread grid

    float acc[8][8];
    #pragma unroll
    for (int i = 0; i < 8; i++)
        #pragma unroll
        for (int j = 0; j < 8; j++) acc[i][j] = 0.f;

    const float* Aptr = A + (row0 + irA) * K + icA;
    const float* Wptr = W + irB * N + col0 + icB;

    for (int k0 = 0; k0 < K; k0 += 8) {
        float4 a4 = *reinterpret_cast<const float4*>(Aptr + k0);
        As[(icA+0)*128 + irA] = a4.x;
        As[(icA+1)*128 + irA] = a4.y;
        As[(icA+2)*128 + irA] = a4.z;
        As[(icA+3)*128 + irA] = a4.w;
        float4 b4 = *reinterpret_cast<const float4*>(Wptr + k0 * N);
        *reinterpret_cast<float4*>(&Bs[irB*128 + icB]) = b4;
        __syncthreads();

        #pragma unroll
        for (int kk = 0; kk < 8; kk++) {
            float4 a0 = *reinterpret_cast<float4*>(&As[kk*128 + tr*8]);
            float4 a1 = *reinterpret_cast<float4*>(&As[kk*128 + tr*8 + 4]);
            float4 b0 = *reinterpret_cast<float4*>(&Bs[kk*128 + tc*8]);
            float4 b1 = *reinterpret_cast<float4*>(&Bs[kk*128 + tc*8 + 4]);
            float ra[8] = {a0.x,a0.y,a0.z,a0.w,a1.x,a1.y,a1.z,a1.w};
            float rb[8] = {b0.x,b0.y,b0.z,b0.w,b1.x,b1.y,b1.z,b1.w};
            #pragma unroll
            for (int i = 0; i < 8; i++)
                #pragma unroll
                for (int j = 0; j < 8; j++)
                    acc[i][j] += ra[i] * rb[j];
        }
        __syncthreads();
    }

    #pragma unroll
    for (int i = 0; i < 8; i++) {
        int r = row0 + tr*8 + i;
        #pragma unroll
        for (int j = 0; j < 8; j += 4) {
            int c = col0 + tc*8 + j;
            float4 o;
            o.x = acc[i][j+0] + bias[c+0];
            o.y = acc[i][j+1] + bias[c+1];
            o.z = acc[i][j+2] + bias[c+2];
            o.w = acc[i][j+3] + bias[c+3];
            if (RELU) {
                o.x = fmaxf(o.x, 0.f); o.y = fmaxf(o.y, 0.f);
                o.z = fmaxf(o.z, 0.f); o.w = fmaxf(o.w, 0.f);
            }
            *reinterpret_cast<float4*>(&C[(long)r * N + c]) = o;
        }
    }
}

// ---------------- flash attention (fp32 SIMT, online softmax) ---------------
// grid (S/64, H, B), 256 threads. Each block: 64 query rows x full key dim.
// Thread (ty,tx) owns rows r_i = ty+16i, cols c_j = tx+16j (strided -> no
// smem bank conflicts with stride-65 padding).
#define LNP 65
__global__ __launch_bounds__(256) void flash_attn_kernel(
    const float* __restrict__ Q, const float* __restrict__ Kg,
    const float* __restrict__ Vg, float* __restrict__ O)
{
    extern __shared__ float sm[];
    float* Qs = sm;                // 64 x 65
    float* Ks = sm + 64*LNP;
    float* Vs = sm + 2*64*LNP;
    float* Ps = sm + 3*64*LNP;

    const int tid = threadIdx.x;
    const int ty = tid >> 4, tx = tid & 15;
    const int qbase = blockIdx.x * 64;
    const int h = blockIdx.y;
    const int b = blockIdx.z;
    const int baseoff = b * SSQ * DDIM + h * DKK;

    // load Q tile, pre-scaled by 1/sqrt(dk) = 0.125
    for (int idx = tid; idx < 64*64; idx += 256) {
        int rr = idx >> 6, cc = idx & 63;
        Qs[rr*LNP + cc] = Q[baseoff + (qbase + rr) * DDIM + cc] * 0.125f;
    }

    float acc[4][4];
    float mrow[4], lrow[4];
    #pragma unroll
    for (int i = 0; i < 4; i++) {
        mrow[i] = -1e30f; lrow[i] = 0.f;
        #pragma unroll
        for (int j = 0; j < 4; j++) acc[i][j] = 0.f;
    }

    for (int kt = 0; kt < SSQ/64; kt++) {
        __syncthreads();   // protect K/V/P from previous iteration's readers
        const int kbase = kt * 64;
        for (int idx = tid; idx < 64*64; idx += 256) {
            int rr = idx >> 6, cc = idx & 63;
            int g = baseoff + (kbase + rr) * DDIM + cc;
            Ks[rr*LNP + cc] = Kg[g];
            Vs[rr*LNP + cc] = Vg[g];
        }
        __syncthreads();

        // S = Q K^T (scaled)
        float s[4][4];
        #pragma unroll
        for (int i = 0; i < 4; i++)
            #pragma unroll
            for (int j = 0; j < 4; j++) s[i][j] = 0.f;
        #pragma unroll 4
        for (int d = 0; d < 64; d++) {
            float qr[4], kr[4];
            #pragma unroll
            for (int i = 0; i < 4; i++) qr[i] = Qs[(ty + 16*i)*LNP + d];
            #pragma unroll
            for (int j = 0; j < 4; j++) kr[j] = Ks[(tx + 16*j)*LNP + d];
            #pragma unroll
            for (int i = 0; i < 4; i++)
                #pragma unroll
                for (int j = 0; j < 4; j++)
                    s[i][j] += qr[i] * kr[j];
        }

        // online softmax per row (16 lanes share a row)
        #pragma unroll
        for (int i = 0; i < 4; i++) {
            float tm = fmaxf(fmaxf(s[i][0], s[i][1]), fmaxf(s[i][2], s[i][3]));
            #pragma unroll
            for (int off = 8; off; off >>= 1)
                tm = fmaxf(tm, __shfl_xor_sync(0xffffffffu, tm, off));
            float mnew = fmaxf(mrow[i], tm);
            float psum = 0.f;
            #pragma unroll
            for (int j = 0; j < 4; j++) {
                s[i][j] = __expf(s[i][j] - mnew);
                psum += s[i][j];
            }
            #pragma unroll
            for (int off = 8; off; off >>= 1)
                psum += __shfl_xor_sync(0xffffffffu, psum, off);
            float fac = __expf(mrow[i] - mnew);
            lrow[i] = lrow[i] * fac + psum;
            mrow[i] = mnew;
            #pragma unroll
            for (int j = 0; j < 4; j++) {
                acc[i][j] *= fac;
                Ps[(ty + 16*i)*LNP + (tx + 16*j)] = s[i][j];
            }
        }
        __syncthreads();

        // O += P @ V
        #pragma unroll 4
        for (int d = 0; d < 64; d++) {
            float pr[4], vr[4];
            #pragma unroll
            for (int i = 0; i < 4; i++) pr[i] = Ps[(ty + 16*i)*LNP + d];
            #pragma unroll
            for (int j = 0; j < 4; j++) vr[j] = Vs[d*LNP + (tx + 16*j)];
            #pragma unroll
            for (int i = 0; i < 4; i++)
                #pragma unroll
                for (int j = 0; j < 4; j++)
                    acc[i][j] += pr[i] * vr[j];
        }
    }

    #pragma unroll
    for (int i = 0; i < 4; i++) {
        float inv = 1.f / lrow[i];
        #pragma unroll
        for (int j = 0; j < 4; j++)
            O[baseoff + (qbase + ty + 16*i) * DDIM + (tx + 16*j)] = acc[i][j] * inv;
    }
}

// ---------------- residual add + LayerNorm (unbiased std, /(std+eps)) ------
__global__ __launch_bounds__(256) void add_ln_kernel(
    const float* __restrict__ A, const float* __restrict__ Bv,
    const float* __restrict__ alpha, const float* __restrict__ gamma,
    float* __restrict__ out)
{
    const int row = blockIdx.x;
    const int tid = threadIdx.x;
    const long base = (long)row * DDIM;

    float v[3];
    float sum = 0.f, sq = 0.f;
    #pragma unroll
    for (int u = 0; u < 3; u++) {
        int c = tid + 256*u;
        float val = A[base + c] + Bv[base + c];
        v[u] = val;
        sum += val;
        sq  += val * val;
    }
    #pragma unroll
    for (int off = 16; off; off >>= 1) {
        sum += __shfl_xor_sync(0xffffffffu, sum, off);
        sq  += __shfl_xor_sync(0xffffffffu, sq,  off);
    }
    __shared__ float rs[8], rq[8];
    __shared__ float sm_mean, sm_inv;
    int warp = tid >> 5, lane = tid & 31;
    if (lane == 0) { rs[warp] = sum; rq[warp] = sq; }
    __syncthreads();
    if (tid == 0) {
        float S = 0.f, Qv = 0.f;
        #pragma unroll
        for (int w = 0; w < 8; w++) { S += rs[w]; Qv += rq[w]; }
        float mean = S * (1.f/768.f);
        float var  = (Qv - 768.f * mean * mean) * (1.f/767.f);
        float sd   = sqrtf(fmaxf(var, 0.f));
        sm_mean = mean;
        sm_inv  = 1.f / (sd + EPSV);
    }
    __syncthreads();
    const float al = alpha[0], ga = gamma[0];
    const float mean = sm_mean, inv = sm_inv;
    #pragma unroll
    for (int u = 0; u < 3; u++) {
        int c = tid + 256*u;
        out[base + c] = al * (v[u] - mean) * inv + ga;
    }
}

// ---------------- launch ----------------------------------------------------
extern "C" void kernel_launch(void* const* d_in, const int* in_sizes, int n_in,
                              void* d_out, int out_size)
{
    const float* x  = (const float*)d_in[0];
    const float* wq = (const float*)d_in[1];
    const float* bq = (const float*)d_in[2];
    const float* wk = (const float*)d_in[3];
    const float* bk = (const float*)d_in[4];
    const float* wv = (const float*)d_in[5];
    const float* bv = (const float*)d_in[6];
    const float* wo = (const float*)d_in[7];
    const float* bo = (const float*)d_in[8];
    const float* w1 = (const float*)d_in[9];
    const float* b1 = (const float*)d_in[10];
    const float* w2 = (const float*)d_in[11];
    const float* b2 = (const float*)d_in[12];
    const float* a1 = (const float*)d_in[13];
    const float* g1 = (const float*)d_in[14];
    const float* a2 = (const float*)d_in[15];
    const float* g2 = (const float*)d_in[16];
    float* out = (float*)d_out;

    float *q, *k, *v, *ctx, *att, *x1, *ffh, *ff2;
    cudaGetSymbolAddress((void**)&q,   g_q);
    cudaGetSymbolAddress((void**)&k,   g_k);
    cudaGetSymbolAddress((void**)&v,   g_v);
    cudaGetSymbolAddress((void**)&ctx, g_ctx);
    cudaGetSymbolAddress((void**)&att, g_att);
    cudaGetSymbolAddress((void**)&x1,  g_x1);
    cudaGetSymbolAddress((void**)&ffh, g_ffh);
    cudaGetSymbolAddress((void**)&ff2, g_ff2);

    const int flash_smem = 4 * 64 * LNP * (int)sizeof(float);  // 66560 B
    cudaFuncSetAttribute(flash_attn_kernel,
                         cudaFuncAttributeMaxDynamicSharedMemorySize, flash_smem);

    dim3 g768(DDIM/128,  MTOT/128);   // (6, 64)
    dim3 g3072(FFD/128,  MTOT/128);   // (24, 64)

    // QKV projections
    sgemm_bias<false><<<g768, 256>>>(x, wq, bq, q, MTOT, DDIM, DDIM);
    sgemm_bias<false><<<g768, 256>>>(x, wk, bk, k, MTOT, DDIM, DDIM);
    sgemm_bias<false><<<g768, 256>>>(x, wv, bv, v, MTOT, DDIM, DDIM);

    // attention
    flash_attn_kernel<<<dim3(SSQ/64, HHD, BB), 256, flash_smem>>>(q, k, v, ctx);

    // output projection + residual LN
    sgemm_bias<false><<<g768, 256>>>(ctx, wo, bo, att, MTOT, DDIM, DDIM);
    add_ln_kernel<<<MTOT, 256>>>(x, att, a1, g1, x1);

    // feedforward + residual LN
    sgemm_bias<true ><<<g3072, 256>>>(x1, w1, b1, ffh, MTOT, FFD, DDIM);
    sgemm_bias<false><<<g768, 256>>>(ffh, w2, b2, ff2, MTOT, DDIM, FFD);
    add_ln_kernel<<<MTOT, 256>>>(x1, ff2, a2, g2, out);
}

// round 8
// speedup vs baseline: 2.0083x; 2.0083x over previous
#include <cuda_runtime.h>
#include <mma.h>
#include <math.h>
#include <cstdint>

using namespace nvcuda;

#define BB   2
#define SSQ  4096
#define DDIM 768
#define HHD  12
#define DKK  64
#define FFD  3072
#define MTOT (BB*SSQ)        // 8192 rows
#define EPSV 1e-5f

// ---------------- scratch (device globals; no allocations allowed) ----------
__device__ float g_q  [MTOT*DDIM];
__device__ float g_k  [MTOT*DDIM];
__device__ float g_v  [MTOT*DDIM];
__device__ float g_ctx[MTOT*DDIM];
__device__ float g_att[MTOT*DDIM];
__device__ float g_x1 [MTOT*DDIM];
__device__ float g_ffh[MTOT*FFD];
__device__ float g_ff2[MTOT*DDIM];

__device__ __forceinline__ uint32_t smem_u32(const void* p) {
    uint32_t a;
    asm("{ .reg .u64 t; cvta.to.shared.u64 t, %1; cvt.u32.u64 %0, t; }"
        : "=r"(a) : "l"(p));
    return a;
}

// ================= wmma tf32 GEMM: C = A[M,K] @ W[K,N] + bias ===============
// Block tile 128x128, K-chunk 32, 2-stage cp.async double buffer.
// 8 warps in 4(m) x 2(n); warp tile 32x64 = 2x4 wmma 16x16x8 fragments.
// A smem: [128][36] fp32 (pad 4); W smem: [32][132] fp32 (pad 4).
#define APAD_LD 36
#define BPAD_LD 132
#define A_STAGE_BYTES (128 * APAD_LD * 4)            // 18432
#define STAGE_BYTES   (A_STAGE_BYTES + 32 * BPAD_LD * 4)  // 18432+16896=35328
#define GEMM_SMEM     (2 * STAGE_BYTES)              // 70656
#define CPAD_LD 132

__device__ __forceinline__ void gemm_load_tiles(
    uint32_t sb, int s, const float* __restrict__ A, const float* __restrict__ W,
    int row0, int col0, int kc, int K, int N, int tid)
{
    const uint32_t aB = sb + s * STAGE_BYTES;
    const uint32_t bB = aB + A_STAGE_BYTES;
    const float* ag = A + (size_t)row0 * K + kc * 32;
    const float* wg = W + (size_t)(kc * 32) * N + col0;
    #pragma unroll
    for (int i = 0; i < 4; i++) {                 // A tile: 128 x 32 floats
        int idx = tid + (i << 8);
        int r = idx >> 3, c4 = idx & 7;           // r 0..127, c4 0..7 (x4 floats)
        asm volatile("cp.async.cg.shared.global [%0], [%1], 16;"
                     :: "r"(aB + r * (APAD_LD*4) + c4 * 16),
                        "l"(ag + (size_t)r * K + c4 * 4) : "memory");
    }
    #pragma unroll
    for (int i = 0; i < 4; i++) {                 // W tile: 32 x 128 floats
        int idx = tid + (i << 8);
        int r = idx >> 5, c4 = idx & 31;          // r 0..31, c4 0..31
        asm volatile("cp.async.cg.shared.global [%0], [%1], 16;"
                     :: "r"(bB + r * (BPAD_LD*4) + c4 * 16),
                        "l"(wg + (size_t)r * N + c4 * 4) : "memory");
    }
    asm volatile("cp.async.commit_group;" ::: "memory");
}

template<bool RELU>
__global__ __launch_bounds__(256, 2) void tf32_wmma_gemm(
    const float* __restrict__ A, const float* __restrict__ W,
    const float* __restrict__ bias, float* __restrict__ C,
    int M, int N, int K)
{
    extern __shared__ char smem[];
    const uint32_t sb = smem_u32(smem);
    const int tid = threadIdx.x;
    const int wid = tid >> 5;
    const int row0 = blockIdx.y << 7, col0 = blockIdx.x << 7;
    const int wm = wid & 3;            // 0..3 -> 32-row strip
    const int wn = wid >> 2;           // 0..1 -> 64-col strip
    const int NK = K >> 5;

    wmma::fragment<wmma::accumulator, 16, 16, 8, float> acc[2][4];
    #pragma unroll
    for (int i = 0; i < 2; i++)
        #pragma unroll
        for (int j = 0; j < 4; j++)
            wmma::fill_fragment(acc[i][j], 0.0f);

    gemm_load_tiles(sb, 0, A, W, row0, col0, 0, K, N, tid);

    for (int kc = 0; kc < NK; ++kc) {
        const int s = kc & 1;
        if (kc + 1 < NK) {
            gemm_load_tiles(sb, s ^ 1, A, W, row0, col0, kc + 1, K, N, tid);
            asm volatile("cp.async.wait_group 1;" ::: "memory");
        } else {
            asm volatile("cp.async.wait_group 0;" ::: "memory");
        }
        __syncthreads();

        const float* As = (const float*)(smem + s * STAGE_BYTES);
        const float* Bs = (const float*)(smem + s * STAGE_BYTES + A_STAGE_BYTES);

        #pragma unroll
        for (int ks = 0; ks < 4; ++ks) {          // 4 x k=8 steps
            const int k8 = ks * 8;
            wmma::fragment<wmma::matrix_a, 16, 16, 8, wmma::precision::tf32,
                           wmma::row_major> af[2];
            wmma::fragment<wmma::matrix_b, 16, 16, 8, wmma::precision::tf32,
                           wmma::row_major> bf[4];
            #pragma unroll
            for (int i = 0; i < 2; i++) {
                wmma::load_matrix_sync(af[i],
                    As + (wm * 32 + 16 * i) * APAD_LD + k8, APAD_LD);
                #pragma unroll
                for (int t = 0; t < af[i].num_elements; t++)
                    af[i].x[t] = wmma::__float_to_tf32(af[i].x[t]);
            }
            #pragma unroll
            for (int j = 0; j < 4; j++) {
                wmma::load_matrix_sync(bf[j],
                    Bs + k8 * BPAD_LD + wn * 64 + 16 * j, BPAD_LD);
                #pragma unroll
                for (int t = 0; t < bf[j].num_elements; t++)
                    bf[j].x[t] = wmma::__float_to_tf32(bf[j].x[t]);
            }
            #pragma unroll
            for (int i = 0; i < 2; i++)
                #pragma unroll
                for (int j = 0; j < 4; j++)
                    wmma::mma_sync(acc[i][j], af[i], bf[j], acc[i][j]);
        }
        __syncthreads();
    }

    // epilogue: accs -> smem -> bias(+relu) -> global
    float* Cs = (float*)smem;
    #pragma unroll
    for (int i = 0; i < 2; i++)
        #pragma unroll
        for (int j = 0; j < 4; j++)
            wmma::store_matrix_sync(
                Cs + (wm * 32 + 16 * i) * CPAD_LD + wn * 64 + 16 * j,
                acc[i][j], CPAD_LD, wmma::mem_row_major);
    __syncthreads();

    const int r = tid >> 1, hf = tid & 1;         // 2 threads per row
    const float* crow = Cs + r * CPAD_LD + hf * 64;
    const int cg0 = col0 + hf * 64;
    float* gout = C + (size_t)(row0 + r) * N + cg0;
    #pragma unroll
    for (int j = 0; j < 16; j++) {
        float4 b4 = *reinterpret_cast<const float4*>(bias + cg0 + j * 4);
        float4 o;
        o.x = crow[j*4 + 0] + b4.x;
        o.y = crow[j*4 + 1] + b4.y;
        o.z = crow[j*4 + 2] + b4.z;
        o.w = crow[j*4 + 3] + b4.w;
        if (RELU) {
            o.x = fmaxf(o.x, 0.f); o.y = fmaxf(o.y, 0.f);
            o.z = fmaxf(o.z, 0.f); o.w = fmaxf(o.w, 0.f);
        }
        *reinterpret_cast<float4*>(gout + j * 4) = o;
    }
}

// ---------------- flash attention (fp32 SIMT, online softmax) ---------------
#define LNP 65
__global__ __launch_bounds__(256) void flash_attn_kernel(
    const float* __restrict__ Q, const float* __restrict__ Kg,
    const float* __restrict__ Vg, float* __restrict__ O)
{
    extern __shared__ float sm[];
    float* Qs = sm;                // 64 x 65
    float* Ks = sm + 64*LNP;
    float* Vs = sm + 2*64*LNP;
    float* Ps = sm + 3*64*LNP;

    const int tid = threadIdx.x;
    const int ty = tid >> 4, tx = tid & 15;
    const int qbase = blockIdx.x * 64;
    const int h = blockIdx.y;
    const int b = blockIdx.z;
    const int baseoff = b * SSQ * DDIM + h * DKK;

    for (int idx = tid; idx < 64*64; idx += 256) {
        int rr = idx >> 6, cc = idx & 63;
        Qs[rr*LNP + cc] = Q[baseoff + (qbase + rr) * DDIM + cc] * 0.125f;
    }

    float acc[4][4];
    float mrow[4], lrow[4];
    #pragma unroll
    for (int i = 0; i < 4; i++) {
        mrow[i] = -1e30f; lrow[i] = 0.f;
        #pragma unroll
        for (int j = 0; j < 4; j++) acc[i][j] = 0.f;
    }

    for (int kt = 0; kt < SSQ/64; kt++) {
        __syncthreads();
        const int kbase = kt * 64;
        for (int idx = tid; idx < 64*64; idx += 256) {
            int rr = idx >> 6, cc = idx & 63;
            int g = baseoff + (kbase + rr) * DDIM + cc;
            Ks[rr*LNP + cc] = Kg[g];
            Vs[rr*LNP + cc] = Vg[g];
        }
        __syncthreads();

        float s[4][4];
        #pragma unroll
        for (int i = 0; i < 4; i++)
            #pragma unroll
            for (int j = 0; j < 4; j++) s[i][j] = 0.f;
        #pragma unroll 4
        for (int d = 0; d < 64; d++) {
            float qr[4], kr[4];
            #pragma unroll
            for (int i = 0; i < 4; i++) qr[i] = Qs[(ty + 16*i)*LNP + d];
            #pragma unroll
            for (int j = 0; j < 4; j++) kr[j] = Ks[(tx + 16*j)*LNP + d];
            #pragma unroll
            for (int i = 0; i < 4; i++)
                #pragma unroll
                for (int j = 0; j < 4; j++)
                    s[i][j] += qr[i] * kr[j];
        }

        #pragma unroll
        for (int i = 0; i < 4; i++) {
            float tm = fmaxf(fmaxf(s[i][0], s[i][1]), fmaxf(s[i][2], s[i][3]));
            #pragma unroll
            for (int off = 8; off; off >>= 1)
                tm = fmaxf(tm, __shfl_xor_sync(0xffffffffu, tm, off));
            float mnew = fmaxf(mrow[i], tm);
            float psum = 0.f;
            #pragma unroll
            for (int j = 0; j < 4; j++) {
                s[i][j] = __expf(s[i][j] - mnew);
                psum += s[i][j];
            }
            #pragma unroll
            for (int off = 8; off; off >>= 1)
                psum += __shfl_xor_sync(0xffffffffu, psum, off);
            float fac = __expf(mrow[i] - mnew);
            lrow[i] = lrow[i] * fac + psum;
            mrow[i] = mnew;
            #pragma unroll
            for (int j = 0; j < 4; j++) {
                acc[i][j] *= fac;
                Ps[(ty + 16*i)*LNP + (tx + 16*j)] = s[i][j];
            }
        }
        __syncthreads();

        #pragma unroll 4
        for (int d = 0; d < 64; d++) {
            float pr[4], vr[4];
            #pragma unroll
            for (int i = 0; i < 4; i++) pr[i] = Ps[(ty + 16*i)*LNP + d];
            #pragma unroll
            for (int j = 0; j < 4; j++) vr[j] = Vs[d*LNP + (tx + 16*j)];
            #pragma unroll
            for (int i = 0; i < 4; i++)
                #pragma unroll
                for (int j = 0; j < 4; j++)
                    acc[i][j] += pr[i] * vr[j];
        }
    }

    #pragma unroll
    for (int i = 0; i < 4; i++) {
        float inv = 1.f / lrow[i];
        #pragma unroll
        for (int j = 0; j < 4; j++)
            O[baseoff + (qbase + ty + 16*i) * DDIM + (tx + 16*j)] = acc[i][j] * inv;
    }
}

// ---------------- residual add + LayerNorm (unbiased std, /(std+eps)) ------
__global__ __launch_bounds__(256) void add_ln_kernel(
    const float* __restrict__ A, const float* __restrict__ Bv,
    const float* __restrict__ alpha, const float* __restrict__ gamma,
    float* __restrict__ out)
{
    const int row = blockIdx.x;
    const int tid = threadIdx.x;
    const long base = (long)row * DDIM;

    float v[3];
    float sum = 0.f, sq = 0.f;
    #pragma unroll
    for (int u = 0; u < 3; u++) {
        int c = tid + 256*u;
        float val = A[base + c] + Bv[base + c];
        v[u] = val;
        sum += val;
        sq  += val * val;
    }
    #pragma unroll
    for (int off = 16; off; off >>= 1) {
        sum += __shfl_xor_sync(0xffffffffu, sum, off);
        sq  += __shfl_xor_sync(0xffffffffu, sq,  off);
    }
    __shared__ float rs[8], rq[8];
    __shared__ float sm_mean, sm_inv;
    int warp = tid >> 5, lane = tid & 31;
    if (lane == 0) { rs[warp] = sum; rq[warp] = sq; }
    __syncthreads();
    if (tid == 0) {
        float S = 0.f, Qv = 0.f;
        #pragma unroll
        for (int w = 0; w < 8; w++) { S += rs[w]; Qv += rq[w]; }
        float mean = S * (1.f/768.f);
        float var  = (Qv - 768.f * mean * mean) * (1.f/767.f);
        float sd   = sqrtf(fmaxf(var, 0.f));
        sm_mean = mean;
        sm_inv  = 1.f / (sd + EPSV);
    }
    __syncthreads();
    const float al = alpha[0], ga = gamma[0];
    const float mean = sm_mean, inv = sm_inv;
    #pragma unroll
    for (int u = 0; u < 3; u++) {
        int c = tid + 256*u;
        out[base + c] = al * (v[u] - mean) * inv + ga;
    }
}

// ---------------- launch ----------------------------------------------------
extern "C" void kernel_launch(void* const* d_in, const int* in_sizes, int n_in,
                              void* d_out, int out_size)
{
    const float* x  = (const float*)d_in[0];
    const float* wq = (const float*)d_in[1];
    const float* bq = (const float*)d_in[2];
    const float* wk = (const float*)d_in[3];
    const float* bk = (const float*)d_in[4];
    const float* wv = (const float*)d_in[5];
    const float* bv = (const float*)d_in[6];
    const float* wo = (const float*)d_in[7];
    const float* bo = (const float*)d_in[8];
    const float* w1 = (const float*)d_in[9];
    const float* b1 = (const float*)d_in[10];
    const float* w2 = (const float*)d_in[11];
    const float* b2 = (const float*)d_in[12];
    const float* a1 = (const float*)d_in[13];
    const float* g1 = (const float*)d_in[14];
    const float* a2 = (const float*)d_in[15];
    const float* g2 = (const float*)d_in[16];
    float* out = (float*)d_out;

    float *q, *k, *v, *ctx, *att, *x1, *ffh, *ff2;
    cudaGetSymbolAddress((void**)&q,   g_q);
    cudaGetSymbolAddress((void**)&k,   g_k);
    cudaGetSymbolAddress((void**)&v,   g_v);
    cudaGetSymbolAddress((void**)&ctx, g_ctx);
    cudaGetSymbolAddress((void**)&att, g_att);
    cudaGetSymbolAddress((void**)&x1,  g_x1);
    cudaGetSymbolAddress((void**)&ffh, g_ffh);
    cudaGetSymbolAddress((void**)&ff2, g_ff2);

    const int flash_smem = 4 * 64 * LNP * (int)sizeof(float);  // 66560 B
    cudaFuncSetAttribute(flash_attn_kernel,
                         cudaFuncAttributeMaxDynamicSharedMemorySize, flash_smem);
    cudaFuncSetAttribute(tf32_wmma_gemm<false>,
                         cudaFuncAttributeMaxDynamicSharedMemorySize, GEMM_SMEM);
    cudaFuncSetAttribute(tf32_wmma_gemm<true>,
                         cudaFuncAttributeMaxDynamicSharedMemorySize, GEMM_SMEM);

    dim3 g768(DDIM/128,  MTOT/128);   // (6, 64)
    dim3 g3072(FFD/128,  MTOT/128);   // (24, 64)

    // QKV projections (tensor cores, tf32)
    tf32_wmma_gemm<false><<<g768, 256, GEMM_SMEM>>>(x, wq, bq, q, MTOT, DDIM, DDIM);
    tf32_wmma_gemm<false><<<g768, 256, GEMM_SMEM>>>(x, wk, bk, k, MTOT, DDIM, DDIM);
    tf32_wmma_gemm<false><<<g768, 256, GEMM_SMEM>>>(x, wv, bv, v, MTOT, DDIM, DDIM);

    // attention (fp32 SIMT flash)
    flash_attn_kernel<<<dim3(SSQ/64, HHD, BB), 256, flash_smem>>>(q, k, v, ctx);

    // output projection + residual LN
    tf32_wmma_gemm<false><<<g768, 256, GEMM_SMEM>>>(ctx, wo, bo, att, MTOT, DDIM, DDIM);
    add_ln_kernel<<<MTOT, 256>>>(x, att, a1, g1, x1);

    // feedforward + residual LN
    tf32_wmma_gemm<true ><<<g3072, 256, GEMM_SMEM>>>(x1, w1, b1, ffh, MTOT, FFD, DDIM);
    tf32_wmma_gemm<false><<<g768, 256, GEMM_SMEM>>>(ffh, w2, b2, ff2, MTOT, DDIM, FFD);
    add_ln_kernel<<<MTOT, 256>>>(x1, ff2, a2, g2, out);
}

// round 10
// speedup vs baseline: 2.7707x; 1.3796x over previous
#include <cuda_runtime.h>
#include <mma.h>
#include <math.h>
#include <cstdint>

using namespace nvcuda;

#define BB   2
#define SSQ  4096
#define DDIM 768
#define HHD  12
#define DKK  64
#define FFD  3072
#define MTOT (BB*SSQ)        // 8192 rows
#define EPSV 1e-5f

// ---------------- scratch (device globals; no allocations allowed) ----------
__device__ float g_q  [MTOT*DDIM];
__device__ float g_k  [MTOT*DDIM];
__device__ float g_v  [MTOT*DDIM];
__device__ float g_ctx[MTOT*DDIM];
__device__ float g_att[MTOT*DDIM];
__device__ float g_x1 [MTOT*DDIM];
__device__ float g_ffh[MTOT*FFD];
__device__ float g_ff2[MTOT*DDIM];

__device__ __forceinline__ uint32_t smem_u32(const void* p) {
    uint32_t a;
    asm("{ .reg .u64 t; cvta.to.shared.u64 t, %1; cvt.u32.u64 %0, t; }"
        : "=r"(a) : "l"(p));
    return a;
}

// ================= wmma tf32 GEMM: C = A[M,K] @ W[K,N] + bias ===============
#define APAD_LD 36
#define BPAD_LD 132
#define A_STAGE_BYTES (128 * APAD_LD * 4)            // 18432
#define STAGE_BYTES   (A_STAGE_BYTES + 32 * BPAD_LD * 4)  // 35328
#define GEMM_SMEM     (2 * STAGE_BYTES)              // 70656
#define CPAD_LD 132

__device__ __forceinline__ void gemm_load_tiles(
    uint32_t sb, int s, const float* __restrict__ A, const float* __restrict__ W,
    int row0, int col0, int kc, int K, int N, int tid)
{
    const uint32_t aB = sb + s * STAGE_BYTES;
    const uint32_t bB = aB + A_STAGE_BYTES;
    const float* ag = A + (size_t)row0 * K + kc * 32;
    const float* wg = W + (size_t)(kc * 32) * N + col0;
    #pragma unroll
    for (int i = 0; i < 4; i++) {                 // A tile: 128 x 32 floats
        int idx = tid + (i << 8);
        int r = idx >> 3, c4 = idx & 7;
        asm volatile("cp.async.cg.shared.global [%0], [%1], 16;"
                     :: "r"(aB + r * (APAD_LD*4) + c4 * 16),
                        "l"(ag + (size_t)r * K + c4 * 4) : "memory");
    }
    #pragma unroll
    for (int i = 0; i < 4; i++) {                 // W tile: 32 x 128 floats
        int idx = tid + (i << 8);
        int r = idx >> 5, c4 = idx & 31;
        asm volatile("cp.async.cg.shared.global [%0], [%1], 16;"
                     :: "r"(bB + r * (BPAD_LD*4) + c4 * 16),
                        "l"(wg + (size_t)r * N + c4 * 4) : "memory");
    }
    asm volatile("cp.async.commit_group;" ::: "memory");
}

template<bool RELU>
__global__ __launch_bounds__(256, 2) void tf32_wmma_gemm(
    const float* __restrict__ A, const float* __restrict__ W,
    const float* __restrict__ bias, float* __restrict__ C,
    int M, int N, int K)
{
    extern __shared__ char smem[];
    const uint32_t sb = smem_u32(smem);
    const int tid = threadIdx.x;
    const int wid = tid >> 5;
    const int row0 = blockIdx.y << 7, col0 = blockIdx.x << 7;
    const int wm = wid & 3;
    const int wn = wid >> 2;
    const int NK = K >> 5;

    wmma::fragment<wmma::accumulator, 16, 16, 8, float> acc[2][4];
    #pragma unroll
    for (int i = 0; i < 2; i++)
        #pragma unroll
        for (int j = 0; j < 4; j++)
            wmma::fill_fragment(acc[i][j], 0.0f);

    gemm_load_tiles(sb, 0, A, W, row0, col0, 0, K, N, tid);

    for (int kc = 0; kc < NK; ++kc) {
        const int s = kc & 1;
        if (kc + 1 < NK) {
            gemm_load_tiles(sb, s ^ 1, A, W, row0, col0, kc + 1, K, N, tid);
            asm volatile("cp.async.wait_group 1;" ::: "memory");
        } else {
            asm volatile("cp.async.wait_group 0;" ::: "memory");
        }
        __syncthreads();

        const float* As = (const float*)(smem + s * STAGE_BYTES);
        const float* Bs = (const float*)(smem + s * STAGE_BYTES + A_STAGE_BYTES);

        #pragma unroll
        for (int ks = 0; ks < 4; ++ks) {
            const int k8 = ks * 8;
            wmma::fragment<wmma::matrix_a, 16, 16, 8, wmma::precision::tf32,
                           wmma::row_major> af[2];
            wmma::fragment<wmma::matrix_b, 16, 16, 8, wmma::precision::tf32,
                           wmma::row_major> bf[4];
            #pragma unroll
            for (int i = 0; i < 2; i++) {
                wmma::load_matrix_sync(af[i],
                    As + (wm * 32 + 16 * i) * APAD_LD + k8, APAD_LD);
                #pragma unroll
                for (int t = 0; t < af[i].num_elements; t++)
                    af[i].x[t] = wmma::__float_to_tf32(af[i].x[t]);
            }
            #pragma unroll
            for (int j = 0; j < 4; j++) {
                wmma::load_matrix_sync(bf[j],
                    Bs + k8 * BPAD_LD + wn * 64 + 16 * j, BPAD_LD);
                #pragma unroll
                for (int t = 0; t < bf[j].num_elements; t++)
                    bf[j].x[t] = wmma::__float_to_tf32(bf[j].x[t]);
            }
            #pragma unroll
            for (int i = 0; i < 2; i++)
                #pragma unroll
                for (int j = 0; j < 4; j++)
                    wmma::mma_sync(acc[i][j], af[i], bf[j], acc[i][j]);
        }
        __syncthreads();
    }

    float* Cs = (float*)smem;
    #pragma unroll
    for (int i = 0; i < 2; i++)
        #pragma unroll
        for (int j = 0; j < 4; j++)
            wmma::store_matrix_sync(
                Cs + (wm * 32 + 16 * i) * CPAD_LD + wn * 64 + 16 * j,
                acc[i][j], CPAD_LD, wmma::mem_row_major);
    __syncthreads();

    const int r = tid >> 1, hf = tid & 1;
    const float* crow = Cs + r * CPAD_LD + hf * 64;
    const int cg0 = col0 + hf * 64;
    float* gout = C + (size_t)(row0 + r) * N + cg0;
    #pragma unroll
    for (int j = 0; j < 16; j++) {
        float4 b4 = *reinterpret_cast<const float4*>(bias + cg0 + j * 4);
        float4 o;
        o.x = crow[j*4 + 0] + b4.x;
        o.y = crow[j*4 + 1] + b4.y;
        o.z = crow[j*4 + 2] + b4.z;
        o.w = crow[j*4 + 3] + b4.w;
        if (RELU) {
            o.x = fmaxf(o.x, 0.f); o.y = fmaxf(o.y, 0.f);
            o.z = fmaxf(o.z, 0.f); o.w = fmaxf(o.w, 0.f);
        }
        *reinterpret_cast<float4*>(gout + j * 4) = o;
    }
}

// ================= flash attention, wmma tf32 ===============================
// Block: 64 q-rows x one head. 8 warps (wm=wid&3 row strip, wn=wid>>2 col half).
// Per 64-key tile: S = Q K^T (wmma, K row-major consumed as col_major B),
// SIMT online softmax (4 threads/row), O += P V (wmma), SIMT accumulate.
// Smem (floats, LDF=72 pad): Qs(->PV) | Ss | Ks x2 | Vs x2  = 6*64*72.
#define LDF 72
#define FA_TILE_FLOATS (64 * LDF)
#define FA_SMEM (6 * FA_TILE_FLOATS * 4)   // 110592 B

__device__ __forceinline__ void fa_load_kv(
    uint32_t ksB, uint32_t vsB, const float* __restrict__ Kg,
    const float* __restrict__ Vg, int baseoff, int kbase, int tid)
{
    #pragma unroll
    for (int i = 0; i < 4; i++) {
        int idx = tid + (i << 8);           // 0..1023
        int rr = idx >> 4, c4 = idx & 15;   // row 0..63, 16B chunk 0..15
        const size_t g = (size_t)baseoff + (size_t)(kbase + rr) * DDIM + c4 * 4;
        uint32_t d = rr * (LDF * 4) + c4 * 16;
        asm volatile("cp.async.cg.shared.global [%0], [%1], 16;"
                     :: "r"(ksB + d), "l"(Kg + g) : "memory");
        asm volatile("cp.async.cg.shared.global [%0], [%1], 16;"
                     :: "r"(vsB + d), "l"(Vg + g) : "memory");
    }
    asm volatile("cp.async.commit_group;" ::: "memory");
}

__global__ __launch_bounds__(256, 2) void flash_wmma_kernel(
    const float* __restrict__ Q, const float* __restrict__ Kg,
    const float* __restrict__ Vg, float* __restrict__ O)
{
    extern __shared__ float sm[];
    float* Qs  = sm;                        // becomes PV buffer after Q frags
    float* Ss  = sm + FA_TILE_FLOATS;
    float* Ks0 = sm + 2 * FA_TILE_FLOATS;   // 2 stages
    float* Vs0 = sm + 4 * FA_TILE_FLOATS;
    const uint32_t ksB0 = smem_u32(Ks0), vsB0 = smem_u32(Vs0);

    const int tid = threadIdx.x;
    const int wid = tid >> 5;
    const int wm = wid & 3, wn = wid >> 2;
    const int r  = tid >> 2;            // softmax row 0..63
    const int c0 = (tid & 3) * 16;      // softmax col start
    const int qbase = blockIdx.x * 64;
    const int baseoff = blockIdx.z * SSQ * DDIM + blockIdx.y * DKK;

    // load Q tile (scaled) and build persistent A fragments
    for (int idx = tid; idx < 64 * 64; idx += 256) {
        int rr = idx >> 6, cc = idx & 63;
        Qs[rr * LDF + cc] = Q[(size_t)baseoff + (size_t)(qbase + rr) * DDIM + cc] * 0.125f;
    }
    __syncthreads();
    wmma::fragment<wmma::matrix_a, 16, 16, 8, wmma::precision::tf32,
                   wmma::row_major> qf[8];
    #pragma unroll
    for (int ks = 0; ks < 8; ks++) {
        wmma::load_matrix_sync(qf[ks], Qs + (16 * wm) * LDF + 8 * ks, LDF);
        #pragma unroll
        for (int t = 0; t < qf[ks].num_elements; t++)
            qf[ks].x[t] = wmma::__float_to_tf32(qf[ks].x[t]);
    }
    __syncthreads();   // Qs now free for PV use

    float m_r = -1e30f, l_r = 0.f;
    float o_acc[16];
    #pragma unroll
    for (int i = 0; i < 16; i++) o_acc[i] = 0.f;

    fa_load_kv(ksB0, vsB0, Kg, Vg, baseoff, 0, tid);

    const int NT = SSQ / 64;
    for (int kt = 0; kt < NT; ++kt) {
        const int s = kt & 1;
        if (kt + 1 < NT) {
            fa_load_kv(ksB0 + (s ^ 1) * FA_TILE_FLOATS * 4,
                       vsB0 + (s ^ 1) * FA_TILE_FLOATS * 4,
                       Kg, Vg, baseoff, (kt + 1) * 64, tid);
            asm volatile("cp.async.wait_group 1;" ::: "memory");
        } else {
            asm volatile("cp.async.wait_group 0;" ::: "memory");
        }
        __syncthreads();

        const float* Ks = Ks0 + s * FA_TILE_FLOATS;
        const float* Vs = Vs0 + s * FA_TILE_FLOATS;

        // ---- S = Q K^T ----
        wmma::fragment<wmma::accumulator, 16, 16, 8, float> sacc[2];
        wmma::fill_fragment(sacc[0], 0.f);
        wmma::fill_fragment(sacc[1], 0.f);
        #pragma unroll
        for (int ks = 0; ks < 8; ks++) {
            #pragma unroll
            for (int j = 0; j < 2; j++) {
                wmma::fragment<wmma::matrix_b, 16, 16, 8, wmma::precision::tf32,
                               wmma::col_major> bf;
                wmma::load_matrix_sync(bf, Ks + (32 * wn + 16 * j) * LDF + 8 * ks, LDF);
                #pragma unroll
                for (int t = 0; t < bf.num_elements; t++)
                    bf.x[t] = wmma::__float_to_tf32(bf.x[t]);
                wmma::mma_sync(sacc[j], qf[ks], bf, sacc[j]);
            }
        }
        #pragma unroll
        for (int j = 0; j < 2; j++)
            wmma::store_matrix_sync(Ss + (16 * wm) * LDF + 32 * wn + 16 * j,
                                    sacc[j], LDF, wmma::mem_row_major);
        __syncthreads();

        // ---- online softmax (4 threads per row) ----
        {
            float sv[16];
            float tmax = -1e30f;
            #pragma unroll
            for (int i = 0; i < 16; i++) {
                sv[i] = Ss[r * LDF + c0 + i];
                tmax = fmaxf(tmax, sv[i]);
            }
            tmax = fmaxf(tmax, __shfl_xor_sync(0xffffffffu, tmax, 1));
            tmax = fmaxf(tmax, __shfl_xor_sync(0xffffffffu, tmax, 2));
            float mnew = fmaxf(m_r, tmax);
            float psum = 0.f;
            #pragma unroll
            for (int i = 0; i < 16; i++) {
                sv[i] = __expf(sv[i] - mnew);
                psum += sv[i];
            }
            psum += __shfl_xor_sync(0xffffffffu, psum, 1);
            psum += __shfl_xor_sync(0xffffffffu, psum, 2);
            float fac = __expf(m_r - mnew);
            l_r = l_r * fac + psum;
            m_r = mnew;
            #pragma unroll
            for (int i = 0; i < 16; i++) {
                Ss[r * LDF + c0 + i] = sv[i];
                o_acc[i] *= fac;
            }
        }
        __syncthreads();

        // ---- PV = P @ V ----
        wmma::fragment<wmma::accumulator, 16, 16, 8, float> oacc[2];
        wmma::fill_fragment(oacc[0], 0.f);
        wmma::fill_fragment(oacc[1], 0.f);
        #pragma unroll
        for (int ks = 0; ks < 8; ks++) {
            wmma::fragment<wmma::matrix_a, 16, 16, 8, wmma::precision::tf32,
                           wmma::row_major> pf;
            wmma::load_matrix_sync(pf, Ss + (16 * wm) * LDF + 8 * ks, LDF);
            #pragma unroll
            for (int t = 0; t < pf.num_elements; t++)
                pf.x[t] = wmma::__float_to_tf32(pf.x[t]);
            #pragma unroll
            for (int j = 0; j < 2; j++) {
                wmma::fragment<wmma::matrix_b, 16, 16, 8, wmma::precision::tf32,
                               wmma::row_major> vf;
                wmma::load_matrix_sync(vf, Vs + (8 * ks) * LDF + 32 * wn + 16 * j, LDF);
                #pragma unroll
                for (int t = 0; t < vf.num_elements; t++)
                    vf.x[t] = wmma::__float_to_tf32(vf.x[t]);
                wmma::mma_sync(oacc[j], pf, vf, oacc[j]);
            }
        }
        #pragma unroll
        for (int j = 0; j < 2; j++)
            wmma::store_matrix_sync(Qs + (16 * wm) * LDF + 32 * wn + 16 * j,
                                    oacc[j], LDF, wmma::mem_row_major);
        __syncthreads();

        // ---- accumulate PV into per-thread O ----
        #pragma unroll
        for (int i = 0; i < 16; i++)
            o_acc[i] += Qs[r * LDF + c0 + i];
        __syncthreads();
    }

    // ---- epilogue ----
    const float inv = 1.f / l_r;
    float* gout = O + (size_t)baseoff + (size_t)(qbase + r) * DDIM + c0;
    #pragma unroll
    for (int j = 0; j < 4; j++) {
        float4 o;
        o.x = o_acc[j*4 + 0] * inv;
        o.y = o_acc[j*4 + 1] * inv;
        o.z = o_acc[j*4 + 2] * inv;
        o.w = o_acc[j*4 + 3] * inv;
        *reinterpret_cast<float4*>(gout + j * 4) = o;
    }
}

// ---------------- residual add + LayerNorm (unbiased std, /(std+eps)) ------
__global__ __launch_bounds__(256) void add_ln_kernel(
    const float* __restrict__ A, const float* __restrict__ Bv,
    const float* __restrict__ alpha, const float* __restrict__ gamma,
    float* __restrict__ out)
{
    const int row = blockIdx.x;
    const int tid = threadIdx.x;
    const long base = (long)row * DDIM;

    float v[3];
    float sum = 0.f, sq = 0.f;
    #pragma unroll
    for (int u = 0; u < 3; u++) {
        int c = tid + 256*u;
        float val = A[base + c] + Bv[base + c];
        v[u] = val;
        sum += val;
        sq  += val * val;
    }
    #pragma unroll
    for (int off = 16; off; off >>= 1) {
        sum += __shfl_xor_sync(0xffffffffu, sum, off);
        sq  += __shfl_xor_sync(0xffffffffu, sq,  off);
    }
    __shared__ float rs[8], rq[8];
    __shared__ float sm_mean, sm_inv;
    int warp = tid >> 5, lane = tid & 31;
    if (lane == 0) { rs[warp] = sum; rq[warp] = sq; }
    __syncthreads();
    if (tid == 0) {
        float S = 0.f, Qv = 0.f;
        #pragma unroll
        for (int w = 0; w < 8; w++) { S += rs[w]; Qv += rq[w]; }
        float mean = S * (1.f/768.f);
        float var  = (Qv - 768.f * mean * mean) * (1.f/767.f);
        float sd   = sqrtf(fmaxf(var, 0.f));
        sm_mean = mean;
        sm_inv  = 1.f / (sd + EPSV);
    }
    __syncthreads();
    const float al = alpha[0], ga = gamma[0];
    const float mean = sm_mean, inv = sm_inv;
    #pragma unroll
    for (int u = 0; u < 3; u++) {
        int c = tid + 256*u;
        out[base + c] = al * (v[u] - mean) * inv + ga;
    }
}

// ---------------- launch ----------------------------------------------------
extern "C" void kernel_launch(void* const* d_in, const int* in_sizes, int n_in,
                              void* d_out, int out_size)
{
    const float* x  = (const float*)d_in[0];
    const float* wq = (const float*)d_in[1];
    const float* bq = (const float*)d_in[2];
    const float* wk = (const float*)d_in[3];
    const float* bk = (const float*)d_in[4];
    const float* wv = (const float*)d_in[5];
    const float* bv = (const float*)d_in[6];
    const float* wo = (const float*)d_in[7];
    const float* bo = (const float*)d_in[8];
    const float* w1 = (const float*)d_in[9];
    const float* b1 = (const float*)d_in[10];
    const float* w2 = (const float*)d_in[11];
    const float* b2 = (const float*)d_in[12];
    const float* a1 = (const float*)d_in[13];
    const float* g1 = (const float*)d_in[14];
    const float* a2 = (const float*)d_in[15];
    const float* g2 = (const float*)d_in[16];
    float* out = (float*)d_out;

    float *q, *k, *v, *ctx, *att, *x1, *ffh, *ff2;
    cudaGetSymbolAddress((void**)&q,   g_q);
    cudaGetSymbolAddress((void**)&k,   g_k);
    cudaGetSymbolAddress((void**)&v,   g_v);
    cudaGetSymbolAddress((void**)&ctx, g_ctx);
    cudaGetSymbolAddress((void**)&att, g_att);
    cudaGetSymbolAddress((void**)&x1,  g_x1);
    cudaGetSymbolAddress((void**)&ffh, g_ffh);
    cudaGetSymbolAddress((void**)&ff2, g_ff2);

    cudaFuncSetAttribute(flash_wmma_kernel,
                         cudaFuncAttributeMaxDynamicSharedMemorySize, FA_SMEM);
    cudaFuncSetAttribute(tf32_wmma_gemm<false>,
                         cudaFuncAttributeMaxDynamicSharedMemorySize, GEMM_SMEM);
    cudaFuncSetAttribute(tf32_wmma_gemm<true>,
                         cudaFuncAttributeMaxDynamicSharedMemorySize, GEMM_SMEM);

    dim3 g768(DDIM/128,  MTOT/128);   // (6, 64)
    dim3 g3072(FFD/128,  MTOT/128);   // (24, 64)

    // QKV projections (tensor cores, tf32)
    tf32_wmma_gemm<false><<<g768, 256, GEMM_SMEM>>>(x, wq, bq, q, MTOT, DDIM, DDIM);
    tf32_wmma_gemm<false><<<g768, 256, GEMM_SMEM>>>(x, wk, bk, k, MTOT, DDIM, DDIM);
    tf32_wmma_gemm<false><<<g768, 256, GEMM_SMEM>>>(x, wv, bv, v, MTOT, DDIM, DDIM);

    // attention (tensor cores, tf32 flash)
    flash_wmma_kernel<<<dim3(SSQ/64, HHD, BB), 256, FA_SMEM>>>(q, k, v, ctx);

    // output projection + residual LN
    tf32_wmma_gemm<false><<<g768, 256, GEMM_SMEM>>>(ctx, wo, bo, att, MTOT, DDIM, DDIM);
    add_ln_kernel<<<MTOT, 256>>>(x, att, a1, g1, x1);

    // feedforward + residual LN
    tf32_wmma_gemm<true ><<<g3072, 256, GEMM_SMEM>>>(x1, w1, b1, ffh, MTOT, FFD, DDIM);
    tf32_wmma_gemm<false><<<g768, 256, GEMM_SMEM>>>(ffh, w2, b2, ff2, MTOT, DDIM, FFD);
    add_ln_kernel<<<MTOT, 256>>>(x1, ff2, a2, g2, out);
}

// round 11
// speedup vs baseline: 4.2925x; 1.5492x over previous
#include <cuda_runtime.h>
#include <mma.h>
#include <math.h>
#include <cstdint>

using namespace nvcuda;

#define BB   2
#define SSQ  4096
#define DDIM 768
#define HHD  12
#define DKK  64
#define FFD  3072
#define MTOT (BB*SSQ)        // 8192 rows
#define EPSV 1e-5f

// ---------------- scratch (device globals; no allocations allowed) ----------
__device__ float g_q  [MTOT*DDIM];
__device__ float g_k  [MTOT*DDIM];
__device__ float g_v  [MTOT*DDIM];
__device__ float g_ctx[MTOT*DDIM];
__device__ float g_att[MTOT*DDIM];
__device__ float g_x1 [MTOT*DDIM];
__device__ float g_ffh[MTOT*FFD];
__device__ float g_ff2[MTOT*DDIM];

__device__ __forceinline__ uint32_t smem_u32(const void* p) {
    uint32_t a;
    asm("{ .reg .u64 t; cvta.to.shared.u64 t, %1; cvt.u32.u64 %0, t; }"
        : "=r"(a) : "l"(p));
    return a;
}

// ================= wmma tf32 GEMM: C = A[M,K] @ W[K,N] + bias ===============
#define APAD_LD 36
#define BPAD_LD 132
#define A_STAGE_BYTES (128 * APAD_LD * 4)            // 18432
#define STAGE_BYTES   (A_STAGE_BYTES + 32 * BPAD_LD * 4)  // 35328
#define GEMM_SMEM     (2 * STAGE_BYTES)              // 70656
#define CPAD_LD 132

__device__ __forceinline__ void gemm_load_tiles(
    uint32_t sb, int s, const float* __restrict__ A, const float* __restrict__ W,
    int row0, int col0, int kc, int K, int N, int tid)
{
    const uint32_t aB = sb + s * STAGE_BYTES;
    const uint32_t bB = aB + A_STAGE_BYTES;
    const float* ag = A + (size_t)row0 * K + kc * 32;
    const float* wg = W + (size_t)(kc * 32) * N + col0;
    #pragma unroll
    for (int i = 0; i < 4; i++) {                 // A tile: 128 x 32 floats
        int idx = tid + (i << 8);
        int r = idx >> 3, c4 = idx & 7;
        asm volatile("cp.async.cg.shared.global [%0], [%1], 16;"
                     :: "r"(aB + r * (APAD_LD*4) + c4 * 16),
                        "l"(ag + (size_t)r * K + c4 * 4) : "memory");
    }
    #pragma unroll
    for (int i = 0; i < 4; i++) {                 // W tile: 32 x 128 floats
        int idx = tid + (i << 8);
        int r = idx >> 5, c4 = idx & 31;
        asm volatile("cp.async.cg.shared.global [%0], [%1], 16;"
                     :: "r"(bB + r * (BPAD_LD*4) + c4 * 16),
                        "l"(wg + (size_t)r * N + c4 * 4) : "memory");
    }
    asm volatile("cp.async.commit_group;" ::: "memory");
}

template<bool RELU>
__global__ __launch_bounds__(256, 2) void tf32_wmma_gemm(
    const float* __restrict__ A, const float* __restrict__ W,
    const float* __restrict__ bias, float* __restrict__ C,
    int M, int N, int K)
{
    extern __shared__ char smem[];
    const uint32_t sb = smem_u32(smem);
    const int tid = threadIdx.x;
    const int wid = tid >> 5;
    const int row0 = blockIdx.y << 7, col0 = blockIdx.x << 7;
    const int wm = wid & 3;
    const int wn = wid >> 2;
    const int NK = K >> 5;

    wmma::fragment<wmma::accumulator, 16, 16, 8, float> acc[2][4];
    #pragma unroll
    for (int i = 0; i < 2; i++)
        #pragma unroll
        for (int j = 0; j < 4; j++)
            wmma::fill_fragment(acc[i][j], 0.0f);

    gemm_load_tiles(sb, 0, A, W, row0, col0, 0, K, N, tid);

    for (int kc = 0; kc < NK; ++kc) {
        const int s = kc & 1;
        if (kc + 1 < NK) {
            gemm_load_tiles(sb, s ^ 1, A, W, row0, col0, kc + 1, K, N, tid);
            asm volatile("cp.async.wait_group 1;" ::: "memory");
        } else {
            asm volatile("cp.async.wait_group 0;" ::: "memory");
        }
        __syncthreads();

        const float* As = (const float*)(smem + s * STAGE_BYTES);
        const float* Bs = (const float*)(smem + s * STAGE_BYTES + A_STAGE_BYTES);

        #pragma unroll
        for (int ks = 0; ks < 4; ++ks) {
            const int k8 = ks * 8;
            wmma::fragment<wmma::matrix_a, 16, 16, 8, wmma::precision::tf32,
                           wmma::row_major> af[2];
            wmma::fragment<wmma::matrix_b, 16, 16, 8, wmma::precision::tf32,
                           wmma::row_major> bf[4];
            #pragma unroll
            for (int i = 0; i < 2; i++) {
                wmma::load_matrix_sync(af[i],
                    As + (wm * 32 + 16 * i) * APAD_LD + k8, APAD_LD);
                #pragma unroll
                for (int t = 0; t < af[i].num_elements; t++)
                    af[i].x[t] = wmma::__float_to_tf32(af[i].x[t]);
            }
            #pragma unroll
            for (int j = 0; j < 4; j++) {
                wmma::load_matrix_sync(bf[j],
                    Bs + k8 * BPAD_LD + wn * 64 + 16 * j, BPAD_LD);
                #pragma unroll
                for (int t = 0; t < bf[j].num_elements; t++)
                    bf[j].x[t] = wmma::__float_to_tf32(bf[j].x[t]);
            }
            #pragma unroll
            for (int i = 0; i < 2; i++)
                #pragma unroll
                for (int j = 0; j < 4; j++)
                    wmma::mma_sync(acc[i][j], af[i], bf[j], acc[i][j]);
        }
        __syncthreads();
    }

    float* Cs = (float*)smem;
    #pragma unroll
    for (int i = 0; i < 2; i++)
        #pragma unroll
        for (int j = 0; j < 4; j++)
            wmma::store_matrix_sync(
                Cs + (wm * 32 + 16 * i) * CPAD_LD + wn * 64 + 16 * j,
                acc[i][j], CPAD_LD, wmma::mem_row_major);
    __syncthreads();

    const int r = tid >> 1, hf = tid & 1;
    const float* crow = Cs + r * CPAD_LD + hf * 64;
    const int cg0 = col0 + hf * 64;
    float* gout = C + (size_t)(row0 + r) * N + cg0;
    #pragma unroll
    for (int j = 0; j < 16; j++) {
        float4 b4 = *reinterpret_cast<const float4*>(bias + cg0 + j * 4);
        float4 o;
        o.x = crow[j*4 + 0] + b4.x;
        o.y = crow[j*4 + 1] + b4.y;
        o.z = crow[j*4 + 2] + b4.z;
        o.w = crow[j*4 + 3] + b4.w;
        if (RELU) {
            o.x = fmaxf(o.x, 0.f); o.y = fmaxf(o.y, 0.f);
            o.z = fmaxf(o.z, 0.f); o.w = fmaxf(o.w, 0.f);
        }
        *reinterpret_cast<float4*>(gout + j * 4) = o;
    }
}

// ================= flash attention, raw mma m16n8k8 tf32 ====================
// Block: 128 q-rows x one head, 8 warps, each warp one m16 strip x full
// 64-key tile. S/P/O live entirely in registers (PTX-documented fragment
// layouts); softmax is intra-warp (4 lanes per row). K/V: 3-stage cp.async
// ring, ONE __syncthreads per tile. K stride 68 / V stride 72 give
// conflict-free fragment gathers.
#define FA_QROWS 128
#define LDK 68
#define LDV 72
#define KSTAGE (64*LDK)     // 4352 floats
#define VSTAGE (64*LDV)     // 4608 floats
#define FA_SMEM ((3*KSTAGE + 3*VSTAGE) * 4)   // 107520 B

__device__ __forceinline__ void mma_tf32(float* d, const uint32_t* a,
                                         const uint32_t* b) {
    asm volatile(
        "mma.sync.aligned.m16n8k8.row.col.f32.tf32.tf32.f32 "
        "{%0,%1,%2,%3}, {%4,%5,%6,%7}, {%8,%9}, {%0,%1,%2,%3};"
        : "+f"(d[0]), "+f"(d[1]), "+f"(d[2]), "+f"(d[3])
        : "r"(a[0]), "r"(a[1]), "r"(a[2]), "r"(a[3]), "r"(b[0]), "r"(b[1]));
}

__device__ __forceinline__ void fa_prefetch(
    uint32_t ksB, uint32_t vsB, int s,
    const float* __restrict__ Kg, const float* __restrict__ Vg,
    int baseoff, int kbase, int tid)
{
    const uint32_t kd = ksB + s * (KSTAGE * 4);
    const uint32_t vd = vsB + s * (VSTAGE * 4);
    #pragma unroll
    for (int i = 0; i < 4; i++) {
        int idx = tid + (i << 8);            // 0..1023
        int rr = idx >> 4, c16 = idx & 15;   // row 0..63, 16B chunk
        size_t g = (size_t)baseoff + (size_t)(kbase + rr) * DDIM + c16 * 4;
        asm volatile("cp.async.cg.shared.global [%0], [%1], 16;"
                     :: "r"(kd + rr * (LDK*4) + c16 * 16), "l"(Kg + g) : "memory");
        asm volatile("cp.async.cg.shared.global [%0], [%1], 16;"
                     :: "r"(vd + rr * (LDV*4) + c16 * 16), "l"(Vg + g) : "memory");
    }
    asm volatile("cp.async.commit_group;" ::: "memory");
}

__global__ __launch_bounds__(256, 2) void flash_mma_kernel(
    const float* __restrict__ Q, const float* __restrict__ Kg,
    const float* __restrict__ Vg, float* __restrict__ O)
{
    extern __shared__ float sm[];
    float* Ksm = sm;                 // 3 x 64 x LDK
    float* Vsm = sm + 3 * KSTAGE;    // 3 x 64 x LDV
    const uint32_t ksB = smem_u32(Ksm);
    const uint32_t vsB = smem_u32(Vsm);

    const int tid  = threadIdx.x;
    const int wid  = tid >> 5;
    const int lane = tid & 31;
    const int grp  = lane >> 2;      // groupID (row within m16)
    const int t    = lane & 3;       // threadID_in_group
    const int qbase = blockIdx.x * FA_QROWS;
    const int baseoff = blockIdx.z * SSQ * DDIM + blockIdx.y * DKK;

    // ---- stage Q (scaled) into K area, build persistent A fragments ----
    for (int idx = tid; idx < FA_QROWS * DKK; idx += 256) {
        int rr = idx >> 6, cc = idx & 63;
        Ksm[rr * LDK + cc] =
            Q[(size_t)baseoff + (size_t)(qbase + rr) * DDIM + cc] * 0.125f;
    }
    __syncthreads();
    uint32_t qa[8][4];
    {
        const int r0 = 16 * wid + grp;
        #pragma unroll
        for (int kc = 0; kc < 8; kc++) {
            qa[kc][0] = __float_as_uint(
                wmma::__float_to_tf32(Ksm[r0 * LDK + 8*kc + t]));
            qa[kc][1] = __float_as_uint(
                wmma::__float_to_tf32(Ksm[(r0 + 8) * LDK + 8*kc + t]));
            qa[kc][2] = __float_as_uint(
                wmma::__float_to_tf32(Ksm[r0 * LDK + 8*kc + t + 4]));
            qa[kc][3] = __float_as_uint(
                wmma::__float_to_tf32(Ksm[(r0 + 8) * LDK + 8*kc + t + 4]));
        }
    }
    __syncthreads();                 // Q staging area now free for K stages

    float m0 = -1e30f, m1 = -1e30f, l0 = 0.f, l1 = 0.f;
    float oacc[8][4];
    #pragma unroll
    for (int nt = 0; nt < 8; nt++)
        #pragma unroll
        for (int c = 0; c < 4; c++) oacc[nt][c] = 0.f;

    const int NT = SSQ / 64;
    fa_prefetch(ksB, vsB, 0, Kg, Vg, baseoff, 0, tid);
    fa_prefetch(ksB, vsB, 1, Kg, Vg, baseoff, 64, tid);

    const int srcA = (lane & ~3) | (t >> 1);
    const int srcB = srcA + 2;
    const bool odd = (t & 1);

    for (int kt = 0; kt < NT; ++kt) {
        const int s = kt % 3;
        if (kt < NT - 1)
            asm volatile("cp.async.wait_group 1;" ::: "memory");
        else
            asm volatile("cp.async.wait_group 0;" ::: "memory");
        __syncthreads();   // stage s visible to all; stage (kt-1)%3 consumed
        if (kt + 2 < NT)
            fa_prefetch(ksB, vsB, (kt + 2) % 3, Kg, Vg, baseoff, (kt + 2) * 64, tid);

        const float* Ks = Ksm + s * KSTAGE;
        const float* Vs = Vsm + s * VSTAGE;

        // ---- S = Q K^T (registers) ----
        float sf[8][4];
        #pragma unroll
        for (int nt = 0; nt < 8; nt++)
            #pragma unroll
            for (int c = 0; c < 4; c++) sf[nt][c] = 0.f;
        #pragma unroll
        for (int kc = 0; kc < 8; kc++) {
            #pragma unroll
            for (int nt = 0; nt < 8; nt++) {
                uint32_t kb[2];
                const float* kp = Ks + (8 * nt + grp) * LDK + 8 * kc + t;
                kb[0] = __float_as_uint(kp[0]);   // tf32 by truncation
                kb[1] = __float_as_uint(kp[4]);
                mma_tf32(sf[nt], qa[kc], kb);
            }
        }

        // ---- online softmax (registers, 4 lanes per row) ----
        {
            float mx0 = -1e30f, mx1 = -1e30f;
            #pragma unroll
            for (int nt = 0; nt < 8; nt++) {
                mx0 = fmaxf(mx0, fmaxf(sf[nt][0], sf[nt][1]));
                mx1 = fmaxf(mx1, fmaxf(sf[nt][2], sf[nt][3]));
            }
            mx0 = fmaxf(mx0, __shfl_xor_sync(0xffffffffu, mx0, 1));
            mx0 = fmaxf(mx0, __shfl_xor_sync(0xffffffffu, mx0, 2));
            mx1 = fmaxf(mx1, __shfl_xor_sync(0xffffffffu, mx1, 1));
            mx1 = fmaxf(mx1, __shfl_xor_sync(0xffffffffu, mx1, 2));
            const float mn0 = fmaxf(m0, mx0), mn1 = fmaxf(m1, mx1);
            const float f0 = __expf(m0 - mn0), f1 = __expf(m1 - mn1);
            float s0 = 0.f, s1 = 0.f;
            #pragma unroll
            for (int nt = 0; nt < 8; nt++) {
                sf[nt][0] = __expf(sf[nt][0] - mn0); s0 += sf[nt][0];
                sf[nt][1] = __expf(sf[nt][1] - mn0); s0 += sf[nt][1];
                sf[nt][2] = __expf(sf[nt][2] - mn1); s1 += sf[nt][2];
                sf[nt][3] = __expf(sf[nt][3] - mn1); s1 += sf[nt][3];
            }
            s0 += __shfl_xor_sync(0xffffffffu, s0, 1);
            s0 += __shfl_xor_sync(0xffffffffu, s0, 2);
            s1 += __shfl_xor_sync(0xffffffffu, s1, 1);
            s1 += __shfl_xor_sync(0xffffffffu, s1, 2);
            l0 = l0 * f0 + s0;  l1 = l1 * f1 + s1;
            m0 = mn0;           m1 = mn1;
            #pragma unroll
            for (int nt = 0; nt < 8; nt++) {
                oacc[nt][0] *= f0; oacc[nt][1] *= f0;
                oacc[nt][2] *= f1; oacc[nt][3] *= f1;
            }
        }

        // ---- O += P V : C-frag -> A-frag permutation via shfl, then mma ----
        #pragma unroll
        for (int kk = 0; kk < 8; kk++) {
            const float c0 = sf[kk][0], c1 = sf[kk][1];
            const float c2 = sf[kk][2], c3 = sf[kk][3];
            const float xA0 = __shfl_sync(0xffffffffu, c0, srcA);
            const float xA1 = __shfl_sync(0xffffffffu, c1, srcA);
            const float xA2 = __shfl_sync(0xffffffffu, c2, srcA);
            const float xA3 = __shfl_sync(0xffffffffu, c3, srcA);
            const float xB0 = __shfl_sync(0xffffffffu, c0, srcB);
            const float xB1 = __shfl_sync(0xffffffffu, c1, srcB);
            const float xB2 = __shfl_sync(0xffffffffu, c2, srcB);
            const float xB3 = __shfl_sync(0xffffffffu, c3, srcB);
            uint32_t pa[4];
            pa[0] = __float_as_uint(odd ? xA1 : xA0);   // (row grp,   key t)
            pa[1] = __float_as_uint(odd ? xA3 : xA2);   // (row grp+8, key t)
            pa[2] = __float_as_uint(odd ? xB1 : xB0);   // (row grp,   key t+4)
            pa[3] = __float_as_uint(odd ? xB3 : xB2);   // (row grp+8, key t+4)
            #pragma unroll
            for (int nt = 0; nt < 8; nt++) {
                uint32_t vb[2];
                const float* vp = Vs + (8 * kk + t) * LDV + 8 * nt + grp;
                vb[0] = __float_as_uint(vp[0]);
                vb[1] = __float_as_uint(vp[4 * LDV]);
                mma_tf32(oacc[nt], pa, vb);
            }
        }
    }

    // ---- epilogue: normalize, store ----
    const float i0 = 1.f / l0, i1 = 1.f / l1;
    const int r0 = qbase + 16 * wid + grp;
    float* o0 = O + (size_t)baseoff + (size_t)r0 * DDIM;
    float* o1 = o0 + (size_t)8 * DDIM;
    #pragma unroll
    for (int nt = 0; nt < 8; nt++) {
        const int col = 8 * nt + 2 * t;
        float2 w0 = { oacc[nt][0] * i0, oacc[nt][1] * i0 };
        float2 w1 = { oacc[nt][2] * i1, oacc[nt][3] * i1 };
        *reinterpret_cast<float2*>(o0 + col) = w0;
        *reinterpret_cast<float2*>(o1 + col) = w1;
    }
}

// ---------------- residual add + LayerNorm (unbiased std, /(std+eps)) ------
__global__ __launch_bounds__(256) void add_ln_kernel(
    const float* __restrict__ A, const float* __restrict__ Bv,
    const float* __restrict__ alpha, const float* __restrict__ gamma,
    float* __restrict__ out)
{
    const int row = blockIdx.x;
    const int tid = threadIdx.x;
    const long base = (long)row * DDIM;

    float v[3];
    float sum = 0.f, sq = 0.f;
    #pragma unroll
    for (int u = 0; u < 3; u++) {
        int c = tid + 256*u;
        float val = A[base + c] + Bv[base + c];
        v[u] = val;
        sum += val;
        sq  += val * val;
    }
    #pragma unroll
    for (int off = 16; off; off >>= 1) {
        sum += __shfl_xor_sync(0xffffffffu, sum, off);
        sq  += __shfl_xor_sync(0xffffffffu, sq,  off);
    }
    __shared__ float rs[8], rq[8];
    __shared__ float sm_mean, sm_inv;
    int warp = tid >> 5, lane = tid & 31;
    if (lane == 0) { rs[warp] = sum; rq[warp] = sq; }
    __syncthreads();
    if (tid == 0) {
        float S = 0.f, Qv = 0.f;
        #pragma unroll
        for (int w = 0; w < 8; w++) { S += rs[w]; Qv += rq[w]; }
        float mean = S * (1.f/768.f);
        float var  = (Qv - 768.f * mean * mean) * (1.f/767.f);
        float sd   = sqrtf(fmaxf(var, 0.f));
        sm_mean = mean;
        sm_inv  = 1.f / (sd + EPSV);
    }
    __syncthreads();
    const float al = alpha[0], ga = gamma[0];
    const float mean = sm_mean, inv = sm_inv;
    #pragma unroll
    for (int u = 0; u < 3; u++) {
        int c = tid + 256*u;
        out[base + c] = al * (v[u] - mean) * inv + ga;
    }
}

// ---------------- launch ----------------------------------------------------
extern "C" void kernel_launch(void* const* d_in, const int* in_sizes, int n_in,
                              void* d_out, int out_size)
{
    const float* x  = (const float*)d_in[0];
    const float* wq = (const float*)d_in[1];
    const float* bq = (const float*)d_in[2];
    const float* wk = (const float*)d_in[3];
    const float* bk = (const float*)d_in[4];
    const float* wv = (const float*)d_in[5];
    const float* bv = (const float*)d_in[6];
    const float* wo = (const float*)d_in[7];
    const float* bo = (const float*)d_in[8];
    const float* w1 = (const float*)d_in[9];
    const float* b1 = (const float*)d_in[10];
    const float* w2 = (const float*)d_in[11];
    const float* b2 = (const float*)d_in[12];
    const float* a1 = (const float*)d_in[13];
    const float* g1 = (const float*)d_in[14];
    const float* a2 = (const float*)d_in[15];
    const float* g2 = (const float*)d_in[16];
    float* out = (float*)d_out;

    float *q, *k, *v, *ctx, *att, *x1, *ffh, *ff2;
    cudaGetSymbolAddress((void**)&q,   g_q);
    cudaGetSymbolAddress((void**)&k,   g_k);
    cudaGetSymbolAddress((void**)&v,   g_v);
    cudaGetSymbolAddress((void**)&ctx, g_ctx);
    cudaGetSymbolAddress((void**)&att, g_att);
    cudaGetSymbolAddress((void**)&x1,  g_x1);
    cudaGetSymbolAddress((void**)&ffh, g_ffh);
    cudaGetSymbolAddress((void**)&ff2, g_ff2);

    cudaFuncSetAttribute(flash_mma_kernel,
                         cudaFuncAttributeMaxDynamicSharedMemorySize, FA_SMEM);
    cudaFuncSetAttribute(tf32_wmma_gemm<false>,
                         cudaFuncAttributeMaxDynamicSharedMemorySize, GEMM_SMEM);
    cudaFuncSetAttribute(tf32_wmma_gemm<true>,
                         cudaFuncAttributeMaxDynamicSharedMemorySize, GEMM_SMEM);

    dim3 g768(DDIM/128,  MTOT/128);   // (6, 64)
    dim3 g3072(FFD/128,  MTOT/128);   // (24, 64)

    // QKV projections (tensor cores, tf32)
    tf32_wmma_gemm<false><<<g768, 256, GEMM_SMEM>>>(x, wq, bq, q, MTOT, DDIM, DDIM);
    tf32_wmma_gemm<false><<<g768, 256, GEMM_SMEM>>>(x, wk, bk, k, MTOT, DDIM, DDIM);
    tf32_wmma_gemm<false><<<g768, 256, GEMM_SMEM>>>(x, wv, bv, v, MTOT, DDIM, DDIM);

    // attention (raw mma tf32, register-resident flash)
    flash_mma_kernel<<<dim3(SSQ/FA_QROWS, HHD, BB), 256, FA_SMEM>>>(q, k, v, ctx);

    // output projection + residual LN
    tf32_wmma_gemm<false><<<g768, 256, GEMM_SMEM>>>(ctx, wo, bo, att, MTOT, DDIM, DDIM);
    add_ln_kernel<<<MTOT, 256>>>(x, att, a1, g1, x1);

    // feedforward + residual LN
    tf32_wmma_gemm<true ><<<g3072, 256, GEMM_SMEM>>>(x1, w1, b1, ffh, MTOT, FFD, DDIM);
    tf32_wmma_gemm<false><<<g768, 256, GEMM_SMEM>>>(ffh, w2, b2, ff2, MTOT, DDIM, FFD);
    add_ln_kernel<<<MTOT, 256>>>(x1, ff2, a2, g2, out);
}